// round 3
// baseline (speedup 1.0000x reference)
#include <cuda_runtime.h>
#include <math.h>

#define BATCH  2
#define SEQ    2048
#define DMODEL 1024
#define NH     16
#define HD     64
#define MROWS  (BATCH*SEQ)   // 4096

// Scratch (no allocations allowed) — 4 x 16 MB fp32
__device__ float g_q[BATCH*SEQ*DMODEL];
__device__ float g_k[BATCH*SEQ*DMODEL];
__device__ float g_v[BATCH*SEQ*DMODEL];
__device__ float g_ctx[BATCH*SEQ*DMODEL];

// ---------------------------------------------------------------------------
// C[M,N] = A[M,K] @ W[N,K]^T + bias[N]
// 64x64 block tile, BK=16, 256 threads, 4x4 per-thread microtile.
// Smem tiles stored k-major (transposed) so the inner loop does float4 LDS.
// ---------------------------------------------------------------------------
__global__ __launch_bounds__(256)
void gemm_nt_bias(const float* __restrict__ A, const float* __restrict__ W,
                  const float* __restrict__ bias, float* __restrict__ C,
                  int M, int N, int K)
{
    __shared__ float As[16][68];   // [k][m], pad to 68 (16B-aligned rows)
    __shared__ float Bs[16][68];   // [k][n]

    const int tid = threadIdx.x;
    const int tx  = tid & 15;
    const int ty  = tid >> 4;
    const int m0  = blockIdx.y * 64;
    const int n0  = blockIdx.x * 64;

    const int lr = tid >> 2;          // 0..63 row within tile
    const int lc = (tid & 3) * 4;     // 0,4,8,12 k-offset

    float acc[4][4];
    #pragma unroll
    for (int i = 0; i < 4; i++)
        #pragma unroll
        for (int j = 0; j < 4; j++) acc[i][j] = 0.f;

    for (int kb = 0; kb < K; kb += 16) {
        float4 av = *(const float4*)&A[(size_t)(m0 + lr) * K + kb + lc];
        float4 wv = *(const float4*)&W[(size_t)(n0 + lr) * K + kb + lc];
        As[lc+0][lr] = av.x; As[lc+1][lr] = av.y; As[lc+2][lr] = av.z; As[lc+3][lr] = av.w;
        Bs[lc+0][lr] = wv.x; Bs[lc+1][lr] = wv.y; Bs[lc+2][lr] = wv.z; Bs[lc+3][lr] = wv.w;
        __syncthreads();

        #pragma unroll
        for (int kk = 0; kk < 16; kk++) {
            float4 a4 = *(const float4*)&As[kk][ty*4];
            float4 b4 = *(const float4*)&Bs[kk][tx*4];
            float ar[4] = {a4.x, a4.y, a4.z, a4.w};
            float br[4] = {b4.x, b4.y, b4.z, b4.w};
            #pragma unroll
            for (int i = 0; i < 4; i++)
                #pragma unroll
                for (int j = 0; j < 4; j++)
                    acc[i][j] += ar[i] * br[j];
        }
        __syncthreads();
    }

    #pragma unroll
    for (int i = 0; i < 4; i++) {
        float4 out;
        const float* bp = &bias[n0 + tx*4];
        out.x = acc[i][0] + bp[0];
        out.y = acc[i][1] + bp[1];
        out.z = acc[i][2] + bp[2];
        out.w = acc[i][3] + bp[3];
        *(float4*)&C[(size_t)(m0 + ty*4 + i) * N + n0 + tx*4] = out;
    }
}

// ---------------------------------------------------------------------------
// Flash attention, fp32. One block = 64 queries of one (b,h).
// Key loop in tiles of 32. Online softmax, width-16 shuffle reductions.
// Q is pre-scaled by 1/sqrt(DK)=0.125 at load.
// Mask is int32 (bool -> int32 in the harness), broadcast over queries.
// ---------------------------------------------------------------------------
__global__ __launch_bounds__(256)
void attn_kernel(const float* __restrict__ Q, const float* __restrict__ Kg,
                 const float* __restrict__ V, const int* __restrict__ mask,
                 float* __restrict__ Ctx)
{
    __shared__ float Qs[64][68];   // [q][d]
    __shared__ float Ks[32][68];   // [k][d]
    __shared__ float Vs[32][64];   // [k][d]
    __shared__ float Ps[64][36];   // [q][k]

    const int tid = threadIdx.x;
    const int tx  = tid & 15;
    const int ty  = tid >> 4;
    const int b   = blockIdx.z;
    const int h   = blockIdx.y;
    const int sq0 = blockIdx.x * 64;

    // Load Q tile (scaled)
    {
        const int r  = tid >> 2;        // 0..63
        const int s4 = tid & 3;
        const float* qrow = Q + (size_t)(b*SEQ + sq0 + r) * DMODEL + h*HD;
        #pragma unroll
        for (int c = 0; c < 4; c++) {
            int seg = s4 + c*4;          // 0..15
            float4 qv = *(const float4*)&qrow[seg*4];
            qv.x *= 0.125f; qv.y *= 0.125f; qv.z *= 0.125f; qv.w *= 0.125f;
            *(float4*)&Qs[r][seg*4] = qv;
        }
    }

    float m_i[4], l_i[4], o[4][4];
    #pragma unroll
    for (int i = 0; i < 4; i++) {
        m_i[i] = -INFINITY; l_i[i] = 0.f;
        #pragma unroll
        for (int j = 0; j < 4; j++) o[i][j] = 0.f;
    }

    const int* mrow = mask + (size_t)b * SEQ;

    for (int kb0 = 0; kb0 < SEQ; kb0 += 32) {
        __syncthreads();   // previous PV reads done before overwriting K/V/P
        // Load K,V tile
        {
            const int r  = tid >> 3;     // 0..31
            const int sg = tid & 7;
            const float* krow = Kg + (size_t)(b*SEQ + kb0 + r) * DMODEL + h*HD;
            const float* vrow = V  + (size_t)(b*SEQ + kb0 + r) * DMODEL + h*HD;
            #pragma unroll
            for (int c = 0; c < 2; c++) {
                int seg = sg + c*8;      // 0..15
                *(float4*)&Ks[r][seg*4] = *(const float4*)&krow[seg*4];
                *(float4*)&Vs[r][seg*4] = *(const float4*)&vrow[seg*4];
            }
        }
        __syncthreads();

        // S = Q K^T (64x32 tile; this thread: rows ty*4+i, cols tx*2+jj)
        float s[4][2];
        #pragma unroll
        for (int i = 0; i < 4; i++) { s[i][0] = 0.f; s[i][1] = 0.f; }

        #pragma unroll
        for (int d0 = 0; d0 < 64; d0 += 4) {
            float4 k0 = *(const float4*)&Ks[tx*2+0][d0];
            float4 k1 = *(const float4*)&Ks[tx*2+1][d0];
            #pragma unroll
            for (int i = 0; i < 4; i++) {
                float4 q4 = *(const float4*)&Qs[ty*4+i][d0];
                s[i][0] += q4.x*k0.x + q4.y*k0.y + q4.z*k0.z + q4.w*k0.w;
                s[i][1] += q4.x*k1.x + q4.y*k1.y + q4.z*k1.z + q4.w*k1.w;
            }
        }

        // Mask (key-position mask, broadcast over queries)
        const bool mk0 = mrow[kb0 + tx*2 + 0] != 0;
        const bool mk1 = mrow[kb0 + tx*2 + 1] != 0;
        #pragma unroll
        for (int i = 0; i < 4; i++) {
            if (!mk0) s[i][0] = -1e9f;
            if (!mk1) s[i][1] = -1e9f;
        }

        // Online softmax update per row
        #pragma unroll
        for (int i = 0; i < 4; i++) {
            float rm = fmaxf(s[i][0], s[i][1]);
            #pragma unroll
            for (int off = 8; off > 0; off >>= 1)
                rm = fmaxf(rm, __shfl_xor_sync(0xffffffffu, rm, off, 16));
            float nm   = fmaxf(m_i[i], rm);
            float corr = __expf(m_i[i] - nm);
            m_i[i] = nm;
            float p0 = __expf(s[i][0] - nm);
            float p1 = __expf(s[i][1] - nm);
            float ls = p0 + p1;
            #pragma unroll
            for (int off = 8; off > 0; off >>= 1)
                ls += __shfl_xor_sync(0xffffffffu, ls, off, 16);
            l_i[i] = l_i[i] * corr + ls;
            o[i][0] *= corr; o[i][1] *= corr; o[i][2] *= corr; o[i][3] *= corr;
            Ps[ty*4+i][tx*2+0] = p0;
            Ps[ty*4+i][tx*2+1] = p1;
        }
        __syncthreads();

        // O += P @ V (this thread: rows ty*4+i, d-cols tx*4+j)
        #pragma unroll 8
        for (int kk = 0; kk < 32; kk++) {
            float4 v4 = *(const float4*)&Vs[kk][tx*4];
            #pragma unroll
            for (int i = 0; i < 4; i++) {
                float p = Ps[ty*4+i][kk];
                o[i][0] += p * v4.x;
                o[i][1] += p * v4.y;
                o[i][2] += p * v4.z;
                o[i][3] += p * v4.w;
            }
        }
    }

    // Epilogue: normalize and write ctx in (b,s,h,dk) layout
    #pragma unroll
    for (int i = 0; i < 4; i++) {
        float inv = 1.f / l_i[i];
        float4 out;
        out.x = o[i][0]*inv; out.y = o[i][1]*inv; out.z = o[i][2]*inv; out.w = o[i][3]*inv;
        *(float4*)&Ctx[(size_t)(b*SEQ + sq0 + ty*4 + i) * DMODEL + h*HD + tx*4] = out;
    }
}

// ---------------------------------------------------------------------------
extern "C" void kernel_launch(void* const* d_in, const int* in_sizes, int n_in,
                              void* d_out, int out_size)
{
    const float* query = (const float*)d_in[0];
    const float* key   = (const float*)d_in[1];
    const float* value = (const float*)d_in[2];
    const int*   mask  = (const int*)d_in[3];      // bool -> int32 in harness
    const float* wq = (const float*)d_in[4];
    const float* bq = (const float*)d_in[5];
    const float* wk = (const float*)d_in[6];
    const float* bk = (const float*)d_in[7];
    const float* wv = (const float*)d_in[8];
    const float* bv = (const float*)d_in[9];
    const float* wo = (const float*)d_in[10];
    const float* bo = (const float*)d_in[11];

    float *qb, *kb, *vb, *cb;
    cudaGetSymbolAddress((void**)&qb, g_q);
    cudaGetSymbolAddress((void**)&kb, g_k);
    cudaGetSymbolAddress((void**)&vb, g_v);
    cudaGetSymbolAddress((void**)&cb, g_ctx);

    dim3 gg(DMODEL/64, MROWS/64);   // (16, 64)
    gemm_nt_bias<<<gg, 256>>>(query, wq, bq, qb, MROWS, DMODEL, DMODEL);
    gemm_nt_bias<<<gg, 256>>>(key,   wk, bk, kb, MROWS, DMODEL, DMODEL);
    gemm_nt_bias<<<gg, 256>>>(value, wv, bv, vb, MROWS, DMODEL, DMODEL);

    attn_kernel<<<dim3(SEQ/64, NH, BATCH), 256>>>(qb, kb, vb, mask, cb);

    gemm_nt_bias<<<gg, 256>>>(cb, wo, bo, (float*)d_out, MROWS, DMODEL, DMODEL);
}

// round 5
// speedup vs baseline: 1.5019x; 1.5019x over previous
#include <cuda_runtime.h>
#include <cuda_bf16.h>
#include <math.h>
#include <stdint.h>

typedef __nv_bfloat16 bf;

#define BATCH 2
#define SEQ   2048
#define DM    1024
#define NH    16
#define HD    64
#define MROWS 4096
#define ZH    32
#define KAUG  3072      // 3*DM
#define KAUGS 192       // 3*HD  (per-head augmented)
#define KAUGP 6144      // 3*SEQ (augmented PV K)

// ---------------------------------------------------------------------------
// Scratch (__device__ globals; no allocations allowed)
// ---------------------------------------------------------------------------
__device__ bf g_xq[MROWS*KAUG];          // input query, A-aug
__device__ bf g_xk[MROWS*KAUG];
__device__ bf g_xv[MROWS*KAUG];
__device__ bf g_wq[DM*KAUG];             // weights, B-aug
__device__ bf g_wk[DM*KAUG];
__device__ bf g_wv[DM*KAUG];
__device__ bf g_wo[DM*KAUG];
__device__ bf g_qa[MROWS*KAUG];          // projected Q, per-head A-aug (pre-scaled)
__device__ bf g_ka[MROWS*KAUG];          // projected K, per-head B-aug
__device__ bf g_vt[ZH*HD*KAUGP];         // projected V^T per head, B-aug
__device__ float g_S[(size_t)ZH*SEQ*SEQ];        // scores fp32
__device__ bf g_pa[(size_t)ZH*SEQ*KAUGP];        // probs, A-aug per head
__device__ bf g_ca[MROWS*KAUG];          // context, A-aug

// ---------------------------------------------------------------------------
// PTX helpers (all valid on plain sm_103: mma.sync / ldmatrix / cp.async)
// ---------------------------------------------------------------------------
__device__ __forceinline__ uint32_t su32(const void* p) {
    uint32_t a;
    asm("{ .reg .u64 t; cvta.to.shared.u64 t, %1; cvt.u32.u64 %0, t; }" : "=r"(a) : "l"(p));
    return a;
}
#define CPASYNC(d, s) asm volatile("cp.async.cg.shared.global [%0], [%1], 16;" :: "r"(d), "l"(s))
#define CPCOMMIT()    asm volatile("cp.async.commit_group;")
#define CPWAIT0()     asm volatile("cp.async.wait_group 0;")
#define CPWAIT1()     asm volatile("cp.async.wait_group 1;")

__device__ __forceinline__ void ldm4(uint32_t* r, uint32_t addr) {
    asm volatile("ldmatrix.sync.aligned.m8n8.x4.shared.b16 {%0,%1,%2,%3}, [%4];"
                 : "=r"(r[0]), "=r"(r[1]), "=r"(r[2]), "=r"(r[3]) : "r"(addr));
}
__device__ __forceinline__ void mma16816(float* c, const uint32_t* a, uint32_t b0, uint32_t b1) {
    asm volatile("mma.sync.aligned.m16n8k16.row.col.f32.bf16.bf16.f32 "
                 "{%0,%1,%2,%3}, {%4,%5,%6,%7}, {%8,%9}, {%0,%1,%2,%3};"
                 : "+f"(c[0]), "+f"(c[1]), "+f"(c[2]), "+f"(c[3])
                 : "r"(a[0]), "r"(a[1]), "r"(a[2]), "r"(a[3]), "r"(b0), "r"(b1));
}
__device__ __forceinline__ void bsplit(float x, bf& h, bf& l) {
    h = __float2bfloat16(x);
    l = __float2bfloat16(x - __bfloat162float(h));
}

// ---------------------------------------------------------------------------
// fp32 -> augmented bf16 splits.  A-role: [hi|lo|hi], B-role: [hi|hi|lo]
// ---------------------------------------------------------------------------
__global__ void splitA(const float* __restrict__ in, bf* __restrict__ out, int n) {
    int i = blockIdx.x * 256 + threadIdx.x;
    if (i >= n) return;
    int r = i >> 10, k = i & 1023;
    bf h, l; bsplit(in[i], h, l);
    size_t b = (size_t)r * KAUG;
    out[b + k] = h; out[b + 1024 + k] = l; out[b + 2048 + k] = h;
}
__global__ void splitB(const float* __restrict__ in, bf* __restrict__ out, int n) {
    int i = blockIdx.x * 256 + threadIdx.x;
    if (i >= n) return;
    int r = i >> 10, k = i & 1023;
    bf h, l; bsplit(in[i], h, l);
    size_t b = (size_t)r * KAUG;
    out[b + k] = h; out[b + 1024 + k] = h; out[b + 2048 + k] = l;
}

// ---------------------------------------------------------------------------
// Warp-MMA bf16 NT GEMM:  C[M,N] = A[M,K'] @ B[N,K']^T
// 128 x NTILE tile, BK=32, 256 threads (8 warps, 4x2), double-buffered cp.async.
// MODE 0: out proj -> fp32 + bias (d_out)
// MODE 1: Q proj   -> per-head A-aug, (v+bias)*alpha
// MODE 2: K proj   -> per-head B-aug, v+bias
// MODE 5: V proj   -> per-head transposed B-aug, v+bias
// MODE 3: scores   -> fp32 per head
// MODE 4: PV       -> ctx A-aug (NTILE=64)
// ---------------------------------------------------------------------------
template<int NTILE, int MODE>
__global__ void __launch_bounds__(256, 1)
mma_gemm(const bf* __restrict__ A, const bf* __restrict__ B,
         const float* __restrict__ bias, float* __restrict__ Cf, bf* __restrict__ Co,
         int Kd, int lda, int ldb, float alpha)
{
    __shared__ __align__(16) bf As[2][128][40];
    __shared__ __align__(16) bf Bs[2][NTILE][40];

    const int tid = threadIdx.x, lane = tid & 31, wid = tid >> 5;
    const int m0 = blockIdx.y * 128, n0 = blockIdx.x * NTILE, z = blockIdx.z;

    const bf* Ap = A; const bf* Bp = B;
    if (MODE == 3) {
        int b = z >> 4, h = z & 15;
        size_t o = (size_t)b * SEQ * KAUG + (size_t)h * KAUGS;
        Ap += o; Bp += o;
    }
    if (MODE == 4) {
        Ap += (size_t)z * SEQ * KAUGP;
        Bp += (size_t)z * HD * KAUGP;
    }
    Ap += (size_t)m0 * lda;
    Bp += (size_t)n0 * ldb;

    auto loadA = [&](int st, int kb) {
        #pragma unroll
        for (int i = 0; i < 2; i++) {
            int c = tid + i * 256;          // 0..511
            int r = c >> 2, cc = (c & 3) * 8;
            CPASYNC(su32(&As[st][r][cc]), Ap + (size_t)r * lda + kb + cc);
        }
    };
    auto loadB = [&](int st, int kb) {
        #pragma unroll
        for (int i = 0; i < NTILE / 64; i++) {
            int c = tid + i * 256;
            int r = c >> 2, cc = (c & 3) * 8;
            CPASYNC(su32(&Bs[st][r][cc]), Bp + (size_t)r * ldb + kb + cc);
        }
    };

    const int wm = wid >> 1, wn = wid & 1;
    constexpr int NW8 = NTILE / 16;          // n8 tiles per warp
    float acc[2][NW8][4];
    #pragma unroll
    for (int i = 0; i < 2; i++)
        #pragma unroll
        for (int j = 0; j < NW8; j++)
            #pragma unroll
            for (int t = 0; t < 4; t++) acc[i][j][t] = 0.f;

    const int frow = ((lane >> 3) & 1) * 8 + (lane & 7);   // ldmatrix lane row
    const int fcol = ((lane >> 4) & 1) * 8;                // ldmatrix lane col

    const int KT = Kd >> 5;
    loadA(0, 0); loadB(0, 0); CPCOMMIT();

    for (int kt = 0; kt < KT; kt++) {
        const int st = kt & 1;
        if (kt + 1 < KT) {
            loadA(st ^ 1, (kt + 1) * 32);
            loadB(st ^ 1, (kt + 1) * 32);
            CPCOMMIT();
            CPWAIT1();
        } else {
            CPWAIT0();
        }
        __syncthreads();

        #pragma unroll
        for (int k16 = 0; k16 < 2; k16++) {
            uint32_t a[2][4];
            #pragma unroll
            for (int i = 0; i < 2; i++)
                ldm4(a[i], su32(&As[st][wm * 32 + i * 16 + frow][k16 * 16 + fcol]));
            #pragma unroll
            for (int j = 0; j < NW8 / 2; j++) {
                uint32_t b4[4];
                ldm4(b4, su32(&Bs[st][wn * (NTILE / 2) + j * 16 + frow][k16 * 16 + fcol]));
                #pragma unroll
                for (int i = 0; i < 2; i++) {
                    mma16816(acc[i][2 * j],     a[i], b4[0], b4[2]);
                    mma16816(acc[i][2 * j + 1], a[i], b4[1], b4[3]);
                }
            }
        }
        __syncthreads();
    }

    // Epilogue: each lane owns pairs (row, n..n+1)
    const int er = lane >> 2, ec = (lane & 3) * 2;
    #pragma unroll
    for (int i = 0; i < 2; i++) {
        #pragma unroll
        for (int j = 0; j < NW8; j++) {
            #pragma unroll
            for (int h2 = 0; h2 < 2; h2++) {
                int rr = m0 + wm * 32 + i * 16 + er + h2 * 8;
                int nb = n0 + wn * (NTILE / 2) + j * 8 + ec;
                float v[2] = { acc[i][j][h2 * 2 + 0], acc[i][j][h2 * 2 + 1] };
                #pragma unroll
                for (int t = 0; t < 2; t++) {
                    int n = nb + t;
                    if (MODE == 0) {
                        Cf[(size_t)rr * DM + n] = v[t] + bias[n];
                    } else if (MODE == 1 || MODE == 2) {
                        float x = v[t] + bias[n];
                        if (MODE == 1) x *= alpha;
                        int h = n >> 6, d = n & 63;
                        size_t base = (size_t)rr * KAUG + h * KAUGS + d;
                        bf hi, lo; bsplit(x, hi, lo);
                        if (MODE == 1) { Co[base] = hi; Co[base + 64] = lo; Co[base + 128] = hi; }
                        else           { Co[base] = hi; Co[base + 64] = hi; Co[base + 128] = lo; }
                    } else if (MODE == 5) {
                        float x = v[t] + bias[n];
                        int h = n >> 6, d = n & 63;
                        int zz = (rr >> 11) * NH + h, s = rr & 2047;
                        size_t base = (size_t)zz * HD * KAUGP + (size_t)d * KAUGP + s;
                        bf hi, lo; bsplit(x, hi, lo);
                        Co[base] = hi; Co[base + 2048] = hi; Co[base + 4096] = lo;
                    } else if (MODE == 3) {
                        Cf[(size_t)z * SEQ * SEQ + (size_t)rr * SEQ + n] = v[t];
                    } else { // MODE 4
                        int col = (z & 15) * HD + n;
                        int rowg = (z >> 4) * SEQ + rr;
                        size_t base = (size_t)rowg * KAUG + col;
                        bf hi, lo; bsplit(v[t], hi, lo);
                        Co[base] = hi; Co[base + 1024] = lo; Co[base + 2048] = hi;
                    }
                }
            }
        }
    }
}

// ---------------------------------------------------------------------------
// Row softmax with mask; writes P in A-aug form.  grid = ZH*SEQ rows.
// ---------------------------------------------------------------------------
__global__ void __launch_bounds__(256)
softmax_kernel(const float* __restrict__ S, const int* __restrict__ mask,
               bf* __restrict__ Pa)
{
    __shared__ float red[8];
    __shared__ float bval[2];
    const size_t row = blockIdx.x;
    const int z = (int)(row >> 11), s = (int)(row & 2047);
    const int tid = threadIdx.x, wid = tid >> 5, lane = tid & 31;
    const float* srow = S + row * SEQ;
    const int* mrow = mask + (size_t)(z >> 4) * SEQ;

    float vals[8];
    float mx = -1e30f;
    #pragma unroll
    for (int i = 0; i < 8; i++) {
        int k = i * 256 + tid;
        float v = srow[k];
        if (mrow[k] == 0) v = -1e9f;
        vals[i] = v;
        mx = fmaxf(mx, v);
    }
    #pragma unroll
    for (int o = 16; o > 0; o >>= 1) mx = fmaxf(mx, __shfl_xor_sync(0xffffffffu, mx, o));
    if (lane == 0) red[wid] = mx;
    __syncthreads();
    if (wid == 0) {
        float v = (lane < 8) ? red[lane] : -1e30f;
        #pragma unroll
        for (int o = 4; o > 0; o >>= 1) v = fmaxf(v, __shfl_xor_sync(0xffffffffu, v, o));
        if (lane == 0) bval[0] = v;
    }
    __syncthreads();
    mx = bval[0];

    float sum = 0.f;
    #pragma unroll
    for (int i = 0; i < 8; i++) { vals[i] = __expf(vals[i] - mx); sum += vals[i]; }
    #pragma unroll
    for (int o = 16; o > 0; o >>= 1) sum += __shfl_xor_sync(0xffffffffu, sum, o);
    if (lane == 0) red[wid] = sum;
    __syncthreads();
    if (wid == 0) {
        float v = (lane < 8) ? red[lane] : 0.f;
        #pragma unroll
        for (int o = 4; o > 0; o >>= 1) v += __shfl_xor_sync(0xffffffffu, v, o);
        if (lane == 0) bval[1] = v;
    }
    __syncthreads();
    const float inv = 1.f / bval[1];

    bf* prow = Pa + (size_t)z * SEQ * KAUGP + (size_t)s * KAUGP;
    #pragma unroll
    for (int i = 0; i < 8; i++) {
        int k = i * 256 + tid;
        bf h, l; bsplit(vals[i] * inv, h, l);
        prow[k] = h; prow[2048 + k] = l; prow[4096 + k] = h;
    }
}

// ---------------------------------------------------------------------------
extern "C" void kernel_launch(void* const* d_in, const int* in_sizes, int n_in,
                              void* d_out, int out_size)
{
    const float* query = (const float*)d_in[0];
    const float* key   = (const float*)d_in[1];
    const float* value = (const float*)d_in[2];
    const int*   mask  = (const int*)d_in[3];
    const float* wq = (const float*)d_in[4];  const float* bq = (const float*)d_in[5];
    const float* wk = (const float*)d_in[6];  const float* bk = (const float*)d_in[7];
    const float* wv = (const float*)d_in[8];  const float* bv = (const float*)d_in[9];
    const float* wo = (const float*)d_in[10]; const float* bo = (const float*)d_in[11];

    #define SYM(p, sname) void* p; cudaGetSymbolAddress(&p, sname)
    SYM(xq, g_xq); SYM(xk, g_xk); SYM(xv, g_xv);
    SYM(awq, g_wq); SYM(awk, g_wk); SYM(awv, g_wv); SYM(awo, g_wo);
    SYM(qa, g_qa); SYM(ka, g_ka); SYM(vt, g_vt);
    SYM(Sb, g_S); SYM(pa, g_pa); SYM(ca, g_ca);
    #undef SYM

    const int NIN = MROWS * DM, NW = DM * DM;
    // 1) split inputs (A-role) and weights (B-role) into augmented form
    splitA<<<NIN / 256, 256>>>(query, (bf*)xq, NIN);
    splitA<<<NIN / 256, 256>>>(key,   (bf*)xk, NIN);
    splitA<<<NIN / 256, 256>>>(value, (bf*)xv, NIN);
    splitB<<<NW / 256, 256>>>(wq, (bf*)awq, NW);
    splitB<<<NW / 256, 256>>>(wk, (bf*)awk, NW);
    splitB<<<NW / 256, 256>>>(wv, (bf*)awv, NW);
    splitB<<<NW / 256, 256>>>(wo, (bf*)awo, NW);

    // 2) projections  (M=4096, N=1024, K'=3072)
    dim3 gp(DM / 128, MROWS / 128);   // (8, 32)
    mma_gemm<128, 1><<<gp, 256>>>((bf*)xq, (bf*)awq, bq, nullptr, (bf*)qa,
                                  KAUG, KAUG, KAUG, 0.125f);
    mma_gemm<128, 2><<<gp, 256>>>((bf*)xk, (bf*)awk, bk, nullptr, (bf*)ka,
                                  KAUG, KAUG, KAUG, 1.0f);
    mma_gemm<128, 5><<<gp, 256>>>((bf*)xv, (bf*)awv, bv, nullptr, (bf*)vt,
                                  KAUG, KAUG, KAUG, 1.0f);

    // 3) scores per head  (M=N=2048, K'=192)
    mma_gemm<128, 3><<<dim3(SEQ / 128, SEQ / 128, ZH), 256>>>(
        (bf*)qa, (bf*)ka, nullptr, (float*)Sb, nullptr, KAUGS, KAUG, KAUG, 1.0f);

    // 4) softmax -> P augmented
    softmax_kernel<<<ZH * SEQ, 256>>>((float*)Sb, mask, (bf*)pa);

    // 5) PV per head  (M=2048, N=64, K'=6144)
    mma_gemm<64, 4><<<dim3(1, SEQ / 128, ZH), 256>>>(
        (bf*)pa, (bf*)vt, nullptr, nullptr, (bf*)ca, KAUGP, KAUGP, KAUGP, 1.0f);

    // 6) output projection -> d_out
    mma_gemm<128, 0><<<gp, 256>>>((bf*)ca, (bf*)awo, bo, (float*)d_out, nullptr,
                                  KAUG, KAUG, KAUG, 1.0f);
}

// round 6
// speedup vs baseline: 2.0256x; 1.3487x over previous
#include <cuda_runtime.h>
#include <cuda_bf16.h>
#include <math.h>
#include <stdint.h>

typedef __nv_bfloat16 bf;

#define BATCH 2
#define SEQ   2048
#define DM    1024
#define NH    16
#define HD    64
#define MROWS 4096
#define ZH    32
#define KAUG  3072      // 3*DM
#define KAUGS 192       // 3*HD (per-head augmented)

// ---------------------------------------------------------------------------
// Scratch (__device__ globals; no allocations allowed)
// ---------------------------------------------------------------------------
__device__ bf g_xq[MROWS*KAUG];          // input query, A-aug
__device__ bf g_xk[MROWS*KAUG];
__device__ bf g_xv[MROWS*KAUG];
__device__ bf g_wq[DM*KAUG];             // weights, B-aug
__device__ bf g_wk[DM*KAUG];
__device__ bf g_wv[DM*KAUG];
__device__ bf g_wo[DM*KAUG];
__device__ bf g_qa[MROWS*KAUG];          // projected Q, per-head A-aug (pre-scaled)
__device__ bf g_ka[MROWS*KAUG];          // projected K, per-head B-aug
__device__ bf g_vth[ZH*HD*SEQ];          // projected V^T per head, hi plane
__device__ bf g_vtl[ZH*HD*SEQ];          // lo plane
__device__ bf g_ca[MROWS*KAUG];          // context, A-aug

// ---------------------------------------------------------------------------
// PTX helpers (plain sm_103-legal: mma.sync / ldmatrix / cp.async)
// ---------------------------------------------------------------------------
__device__ __forceinline__ uint32_t su32(const void* p) {
    uint32_t a;
    asm("{ .reg .u64 t; cvta.to.shared.u64 t, %1; cvt.u32.u64 %0, t; }" : "=r"(a) : "l"(p));
    return a;
}
#define CPASYNC(d, s) asm volatile("cp.async.cg.shared.global [%0], [%1], 16;" :: "r"(d), "l"(s))
#define CPCOMMIT()    asm volatile("cp.async.commit_group;")
#define CPWAIT0()     asm volatile("cp.async.wait_group 0;")
#define CPWAIT1()     asm volatile("cp.async.wait_group 1;")

__device__ __forceinline__ void ldm4(uint32_t* r, uint32_t addr) {
    asm volatile("ldmatrix.sync.aligned.m8n8.x4.shared.b16 {%0,%1,%2,%3}, [%4];"
                 : "=r"(r[0]), "=r"(r[1]), "=r"(r[2]), "=r"(r[3]) : "r"(addr));
}
__device__ __forceinline__ void mma16816(float* c, const uint32_t* a, uint32_t b0, uint32_t b1) {
    asm volatile("mma.sync.aligned.m16n8k16.row.col.f32.bf16.bf16.f32 "
                 "{%0,%1,%2,%3}, {%4,%5,%6,%7}, {%8,%9}, {%0,%1,%2,%3};"
                 : "+f"(c[0]), "+f"(c[1]), "+f"(c[2]), "+f"(c[3])
                 : "r"(a[0]), "r"(a[1]), "r"(a[2]), "r"(a[3]), "r"(b0), "r"(b1));
}
__device__ __forceinline__ void bsplit(float x, bf& h, bf& l) {
    h = __float2bfloat16(x);
    l = __float2bfloat16(x - __bfloat162float(h));
}
__device__ __forceinline__ float bhi(float x) {          // round-trip through bf16
    return __bfloat162float(__float2bfloat16(x));
}
__device__ __forceinline__ uint32_t pk2(float lo, float hi) {   // {lo@bits0-15, hi@bits16-31}
    uint32_t r;
    asm("cvt.rn.bf16x2.f32 %0, %1, %2;" : "=r"(r) : "f"(hi), "f"(lo));
    return r;
}

// ---------------------------------------------------------------------------
// fp32 -> augmented bf16 splits.  A-role: [hi|lo|hi], B-role: [hi|hi|lo]
// ---------------------------------------------------------------------------
__global__ void splitA(const float* __restrict__ in, bf* __restrict__ out, int n) {
    int i = blockIdx.x * 256 + threadIdx.x;
    if (i >= n) return;
    int r = i >> 10, k = i & 1023;
    bf h, l; bsplit(in[i], h, l);
    size_t b = (size_t)r * KAUG;
    out[b + k] = h; out[b + 1024 + k] = l; out[b + 2048 + k] = h;
}
__global__ void splitB(const float* __restrict__ in, bf* __restrict__ out, int n) {
    int i = blockIdx.x * 256 + threadIdx.x;
    if (i >= n) return;
    int r = i >> 10, k = i & 1023;
    bf h, l; bsplit(in[i], h, l);
    size_t b = (size_t)r * KAUG;
    out[b + k] = h; out[b + 1024 + k] = h; out[b + 2048 + k] = l;
}

// ---------------------------------------------------------------------------
// Warp-MMA bf16 NT GEMM (projections + out-proj), 128x128 tile, BK=32.
// MODE 0: out proj -> fp32 + bias (d_out)
// MODE 1: Q proj   -> per-head A-aug, (v+bias)*alpha
// MODE 2: K proj   -> per-head B-aug, v+bias
// MODE 5: V proj   -> per-head transposed hi/lo planes, v+bias
// ---------------------------------------------------------------------------
template<int MODE>
__global__ void __launch_bounds__(256, 1)
mma_gemm(const bf* __restrict__ A, const bf* __restrict__ B,
         const float* __restrict__ bias, float* __restrict__ Cf,
         bf* __restrict__ Co, bf* __restrict__ Co2,
         int Kd, float alpha)
{
    __shared__ __align__(16) bf As[2][128][40];
    __shared__ __align__(16) bf Bs[2][128][40];

    const int tid = threadIdx.x, lane = tid & 31, wid = tid >> 5;
    const int m0 = blockIdx.y * 128, n0 = blockIdx.x * 128;

    const bf* Ap = A + (size_t)m0 * KAUG;
    const bf* Bp = B + (size_t)n0 * KAUG;

    auto loadA = [&](int st, int kb) {
        #pragma unroll
        for (int i = 0; i < 2; i++) {
            int c = tid + i * 256;
            int r = c >> 2, cc = (c & 3) * 8;
            CPASYNC(su32(&As[st][r][cc]), Ap + (size_t)r * KAUG + kb + cc);
        }
    };
    auto loadB = [&](int st, int kb) {
        #pragma unroll
        for (int i = 0; i < 2; i++) {
            int c = tid + i * 256;
            int r = c >> 2, cc = (c & 3) * 8;
            CPASYNC(su32(&Bs[st][r][cc]), Bp + (size_t)r * KAUG + kb + cc);
        }
    };

    const int wm = wid >> 1, wn = wid & 1;
    float acc[2][8][4];
    #pragma unroll
    for (int i = 0; i < 2; i++)
        #pragma unroll
        for (int j = 0; j < 8; j++)
            #pragma unroll
            for (int t = 0; t < 4; t++) acc[i][j][t] = 0.f;

    const int frow = ((lane >> 3) & 1) * 8 + (lane & 7);
    const int fcol = ((lane >> 4) & 1) * 8;

    const int KT = Kd >> 5;
    loadA(0, 0); loadB(0, 0); CPCOMMIT();

    for (int kt = 0; kt < KT; kt++) {
        const int st = kt & 1;
        if (kt + 1 < KT) {
            loadA(st ^ 1, (kt + 1) * 32);
            loadB(st ^ 1, (kt + 1) * 32);
            CPCOMMIT();
            CPWAIT1();
        } else {
            CPWAIT0();
        }
        __syncthreads();

        #pragma unroll
        for (int k16 = 0; k16 < 2; k16++) {
            uint32_t a[2][4];
            #pragma unroll
            for (int i = 0; i < 2; i++)
                ldm4(a[i], su32(&As[st][wm * 32 + i * 16 + frow][k16 * 16 + fcol]));
            #pragma unroll
            for (int j = 0; j < 4; j++) {
                uint32_t b4[4];
                ldm4(b4, su32(&Bs[st][wn * 64 + j * 16 + frow][k16 * 16 + fcol]));
                #pragma unroll
                for (int i = 0; i < 2; i++) {
                    mma16816(acc[i][2 * j],     a[i], b4[0], b4[2]);
                    mma16816(acc[i][2 * j + 1], a[i], b4[1], b4[3]);
                }
            }
        }
        __syncthreads();
    }

    const int er = lane >> 2, ec = (lane & 3) * 2;
    #pragma unroll
    for (int i = 0; i < 2; i++) {
        #pragma unroll
        for (int j = 0; j < 8; j++) {
            #pragma unroll
            for (int h2 = 0; h2 < 2; h2++) {
                int rr = m0 + wm * 32 + i * 16 + er + h2 * 8;
                int nb = n0 + wn * 64 + j * 8 + ec;
                float v[2] = { acc[i][j][h2 * 2 + 0], acc[i][j][h2 * 2 + 1] };
                #pragma unroll
                for (int t = 0; t < 2; t++) {
                    int n = nb + t;
                    if (MODE == 0) {
                        Cf[(size_t)rr * DM + n] = v[t] + bias[n];
                    } else if (MODE == 1 || MODE == 2) {
                        float x = v[t] + bias[n];
                        if (MODE == 1) x *= alpha;
                        int h = n >> 6, d = n & 63;
                        size_t base = (size_t)rr * KAUG + h * KAUGS + d;
                        bf hi, lo; bsplit(x, hi, lo);
                        if (MODE == 1) { Co[base] = hi; Co[base + 64] = lo; Co[base + 128] = hi; }
                        else           { Co[base] = hi; Co[base + 64] = hi; Co[base + 128] = lo; }
                    } else { // MODE 5: V -> transposed hi/lo planes
                        float x = v[t] + bias[n];
                        int h = n >> 6, d = n & 63;
                        int zz = (rr >> 11) * NH + h, s = rr & 2047;
                        size_t base = (size_t)zz * HD * SEQ + (size_t)d * SEQ + s;
                        bf hi, lo; bsplit(x, hi, lo);
                        Co[base] = hi; Co2[base] = lo;
                    }
                }
            }
        }
    }
}

// ---------------------------------------------------------------------------
// Fused flash attention, warp-MMA. Block = 128 queries x 1 head (z).
// Key tiles of 64; S via aug Q(192)·K-aug; online softmax in regs;
// PV = Ph·Vh + Pl·Vh + Ph·Vl with V hi/lo planes. ctx written A-aug.
// 256 threads, warp w owns rows w*16..w*16+15.
// ---------------------------------------------------------------------------
#define QS_ELE 0
#define KS_ELE (128*200)                 // after Q (128x200)
#define VS_ELE (KS_ELE + 2*64*200)       // after K (2 buf x 64x200)
#define MSK_BYTE ((VS_ELE + 2*2*64*72) * 2)
#define FLG_BYTE (MSK_BYTE + 2048*4)
#define SMEM_TOTAL_FA (FLG_BYTE + 32*4)

__global__ void __launch_bounds__(256, 1)
flash_attn(const bf* __restrict__ Qa, const bf* __restrict__ Ka,
           const bf* __restrict__ Vh, const bf* __restrict__ Vl,
           const int* __restrict__ mask, bf* __restrict__ Ca)
{
    extern __shared__ __align__(16) bf sm[];
    bf* Qs = sm + QS_ELE;
    bf* Ks = sm + KS_ELE;
    bf* Vs = sm + VS_ELE;
    int* msk = (int*)((char*)sm + MSK_BYTE);
    int* flg = (int*)((char*)sm + FLG_BYTE);

    const int tid = threadIdx.x, lane = tid & 31, w = tid >> 5;
    const int qb = blockIdx.x, z = blockIdx.y;
    const int b = z >> 4, h = z & 15;

    const bf* Qp  = Qa + ((size_t)(b * SEQ + qb * 128)) * KAUG + h * KAUGS;
    const bf* Kp  = Ka + ((size_t)(b * SEQ)) * KAUG + h * KAUGS;
    const bf* Vhp = Vh + (size_t)z * HD * SEQ;
    const bf* Vlp = Vl + (size_t)z * HD * SEQ;

    if (tid < 32) flg[tid] = 0;
    __syncthreads();
    #pragma unroll
    for (int i = 0; i < 8; i++) {
        int k = tid + i * 256;
        int m = mask[b * SEQ + k];
        msk[k] = m;
        if (m == 0) flg[k >> 6] = 1;
    }

    // Q tile (128 x 192) -> smem
    {
        int r = tid >> 1, q = tid & 1;
        #pragma unroll
        for (int i = 0; i < 12; i++) {
            int cc = (q + i * 2) * 8;
            CPASYNC(su32(Qs + r * 200 + cc), Qp + (size_t)r * KAUG + cc);
        }
    }
    auto loadKV = [&](int kb, int st) {
        int r = tid >> 2, q = tid & 3;
        #pragma unroll
        for (int i = 0; i < 6; i++) {            // K: 64 x 192
            int cc = (q + i * 4) * 8;
            CPASYNC(su32(Ks + st * 12800 + r * 200 + cc),
                    Kp + (size_t)(kb * 64 + r) * KAUG + cc);
        }
        #pragma unroll
        for (int i = 0; i < 2; i++) {            // V hi+lo: 64 x 64 each
            int cc = (q + i * 4) * 8;
            CPASYNC(su32(Vs + st * 9216 + r * 72 + cc),
                    Vhp + (size_t)r * SEQ + kb * 64 + cc);
            CPASYNC(su32(Vs + st * 9216 + 4608 + r * 72 + cc),
                    Vlp + (size_t)r * SEQ + kb * 64 + cc);
        }
    };
    loadKV(0, 0); CPCOMMIT();

    const int frow = ((lane >> 3) & 1) * 8 + (lane & 7);
    const int fcol = ((lane >> 4) & 1) * 8;
    const int er = lane >> 2, ec = (lane & 3) * 2;

    uint32_t qf[12][4];
    float Oa[8][4];
    #pragma unroll
    for (int j = 0; j < 8; j++)
        #pragma unroll
        for (int t = 0; t < 4; t++) Oa[j][t] = 0.f;
    float mrow[2] = { -1e30f, -1e30f }, lrow[2] = { 0.f, 0.f };

    for (int kb = 0; kb < 32; kb++) {
        const int st = kb & 1;
        if (kb + 1 < 32) { loadKV(kb + 1, st ^ 1); CPCOMMIT(); CPWAIT1(); }
        else             { CPWAIT0(); }
        __syncthreads();
        if (kb == 0) {
            #pragma unroll
            for (int k16 = 0; k16 < 12; k16++)
                ldm4(qf[k16], su32(Qs + (w * 16 + frow) * 200 + k16 * 16 + fcol));
        }

        // ---- S = Qaug · Kaug^T (16 x 64 per warp) ----
        float Sa[8][4];
        #pragma unroll
        for (int j = 0; j < 8; j++)
            #pragma unroll
            for (int t = 0; t < 4; t++) Sa[j][t] = 0.f;

        const bf* kbuf = Ks + st * 12800;
        #pragma unroll
        for (int j = 0; j < 4; j++) {
            #pragma unroll
            for (int k16 = 0; k16 < 12; k16++) {
                uint32_t b4[4];
                ldm4(b4, su32(kbuf + (j * 16 + frow) * 200 + k16 * 16 + fcol));
                mma16816(Sa[2 * j],     qf[k16], b4[0], b4[2]);
                mma16816(Sa[2 * j + 1], qf[k16], b4[1], b4[3]);
            }
        }

        // ---- mask ----
        if (flg[kb]) {
            #pragma unroll
            for (int j = 0; j < 8; j++) {
                int c0 = kb * 64 + j * 8 + ec;
                if (!msk[c0])     { Sa[j][0] = -1e9f; Sa[j][2] = -1e9f; }
                if (!msk[c0 + 1]) { Sa[j][1] = -1e9f; Sa[j][3] = -1e9f; }
            }
        }

        // ---- online softmax (rows er, er+8) ----
        float mx0 = -1e30f, mx1 = -1e30f;
        #pragma unroll
        for (int j = 0; j < 8; j++) {
            mx0 = fmaxf(mx0, fmaxf(Sa[j][0], Sa[j][1]));
            mx1 = fmaxf(mx1, fmaxf(Sa[j][2], Sa[j][3]));
        }
        #pragma unroll
        for (int o = 1; o <= 2; o <<= 1) {
            mx0 = fmaxf(mx0, __shfl_xor_sync(0xffffffffu, mx0, o));
            mx1 = fmaxf(mx1, __shfl_xor_sync(0xffffffffu, mx1, o));
        }
        float nm0 = fmaxf(mrow[0], mx0), nm1 = fmaxf(mrow[1], mx1);
        float cor0 = __expf(mrow[0] - nm0), cor1 = __expf(mrow[1] - nm1);
        mrow[0] = nm0; mrow[1] = nm1;

        float rs0 = 0.f, rs1 = 0.f;
        #pragma unroll
        for (int j = 0; j < 8; j++) {
            Sa[j][0] = __expf(Sa[j][0] - nm0); rs0 += Sa[j][0];
            Sa[j][1] = __expf(Sa[j][1] - nm0); rs0 += Sa[j][1];
            Sa[j][2] = __expf(Sa[j][2] - nm1); rs1 += Sa[j][2];
            Sa[j][3] = __expf(Sa[j][3] - nm1); rs1 += Sa[j][3];
        }
        #pragma unroll
        for (int o = 1; o <= 2; o <<= 1) {
            rs0 += __shfl_xor_sync(0xffffffffu, rs0, o);
            rs1 += __shfl_xor_sync(0xffffffffu, rs1, o);
        }
        lrow[0] = lrow[0] * cor0 + rs0;
        lrow[1] = lrow[1] * cor1 + rs1;
        #pragma unroll
        for (int j = 0; j < 8; j++) {
            Oa[j][0] *= cor0; Oa[j][1] *= cor0;
            Oa[j][2] *= cor1; Oa[j][3] *= cor1;
        }

        // ---- PV: O += Ph·Vh + Pl·Vh + Ph·Vl ----
        const bf* vh = Vs + st * 9216;
        const bf* vl = vh + 4608;
        #pragma unroll
        for (int c = 0; c < 4; c++) {
            float a0 = Sa[2*c][0], a1 = Sa[2*c][1], a2 = Sa[2*c][2], a3 = Sa[2*c][3];
            float b0 = Sa[2*c+1][0], b1 = Sa[2*c+1][1], b2 = Sa[2*c+1][2], b3 = Sa[2*c+1][3];
            uint32_t ph[4], pl[4];
            ph[0] = pk2(a0, a1); ph[1] = pk2(a2, a3);
            ph[2] = pk2(b0, b1); ph[3] = pk2(b2, b3);
            pl[0] = pk2(a0 - bhi(a0), a1 - bhi(a1));
            pl[1] = pk2(a2 - bhi(a2), a3 - bhi(a3));
            pl[2] = pk2(b0 - bhi(b0), b1 - bhi(b1));
            pl[3] = pk2(b2 - bhi(b2), b3 - bhi(b3));
            #pragma unroll
            for (int t = 0; t < 4; t++) {
                uint32_t bh4[4], bl4[4];
                ldm4(bh4, su32(vh + (t * 16 + frow) * 72 + c * 16 + fcol));
                ldm4(bl4, su32(vl + (t * 16 + frow) * 72 + c * 16 + fcol));
                mma16816(Oa[2 * t],     ph, bh4[0], bh4[2]);
                mma16816(Oa[2 * t + 1], ph, bh4[1], bh4[3]);
                mma16816(Oa[2 * t],     pl, bh4[0], bh4[2]);
                mma16816(Oa[2 * t + 1], pl, bh4[1], bh4[3]);
                mma16816(Oa[2 * t],     ph, bl4[0], bl4[2]);
                mma16816(Oa[2 * t + 1], ph, bl4[1], bl4[3]);
            }
        }
        __syncthreads();
    }

    // ---- epilogue: normalize, write ctx A-aug ----
    float i0 = 1.f / lrow[0], i1 = 1.f / lrow[1];
    int r0g = b * SEQ + qb * 128 + w * 16 + er;
    bf* crow0 = Ca + (size_t)r0g * KAUG + h * 64;
    bf* crow1 = crow0 + (size_t)8 * KAUG;
    #pragma unroll
    for (int j = 0; j < 8; j++) {
        int d0 = j * 8 + ec;
        float v00 = Oa[j][0] * i0, v01 = Oa[j][1] * i0;
        float v10 = Oa[j][2] * i1, v11 = Oa[j][3] * i1;
        bf h00, l00, h01, l01, h10, l10, h11, l11;
        bsplit(v00, h00, l00); bsplit(v01, h01, l01);
        bsplit(v10, h10, l10); bsplit(v11, h11, l11);
        *(__nv_bfloat162*)(crow0 + d0)        = __nv_bfloat162(h00, h01);
        *(__nv_bfloat162*)(crow0 + 1024 + d0) = __nv_bfloat162(l00, l01);
        *(__nv_bfloat162*)(crow0 + 2048 + d0) = __nv_bfloat162(h00, h01);
        *(__nv_bfloat162*)(crow1 + d0)        = __nv_bfloat162(h10, h11);
        *(__nv_bfloat162*)(crow1 + 1024 + d0) = __nv_bfloat162(l10, l11);
        *(__nv_bfloat162*)(crow1 + 2048 + d0) = __nv_bfloat162(h10, h11);
    }
}

// ---------------------------------------------------------------------------
extern "C" void kernel_launch(void* const* d_in, const int* in_sizes, int n_in,
                              void* d_out, int out_size)
{
    const float* query = (const float*)d_in[0];
    const float* key   = (const float*)d_in[1];
    const float* value = (const float*)d_in[2];
    const int*   mask  = (const int*)d_in[3];
    const float* wq = (const float*)d_in[4];  const float* bq = (const float*)d_in[5];
    const float* wk = (const float*)d_in[6];  const float* bk = (const float*)d_in[7];
    const float* wv = (const float*)d_in[8];  const float* bv = (const float*)d_in[9];
    const float* wo = (const float*)d_in[10]; const float* bo = (const float*)d_in[11];

    #define SYM(p, sname) void* p; cudaGetSymbolAddress(&p, sname)
    SYM(xq, g_xq); SYM(xk, g_xk); SYM(xv, g_xv);
    SYM(awq, g_wq); SYM(awk, g_wk); SYM(awv, g_wv); SYM(awo, g_wo);
    SYM(qa, g_qa); SYM(ka, g_ka); SYM(vth, g_vth); SYM(vtl, g_vtl);
    SYM(ca, g_ca);
    #undef SYM

    const int NIN = MROWS * DM, NW = DM * DM;
    splitA<<<NIN / 256, 256>>>(query, (bf*)xq, NIN);
    splitA<<<NIN / 256, 256>>>(key,   (bf*)xk, NIN);
    splitA<<<NIN / 256, 256>>>(value, (bf*)xv, NIN);
    splitB<<<NW / 256, 256>>>(wq, (bf*)awq, NW);
    splitB<<<NW / 256, 256>>>(wk, (bf*)awk, NW);
    splitB<<<NW / 256, 256>>>(wv, (bf*)awv, NW);
    splitB<<<NW / 256, 256>>>(wo, (bf*)awo, NW);

    dim3 gp(DM / 128, MROWS / 128);   // (8, 32)
    mma_gemm<1><<<gp, 256>>>((bf*)xq, (bf*)awq, bq, nullptr, (bf*)qa, nullptr, KAUG, 0.125f);
    mma_gemm<2><<<gp, 256>>>((bf*)xk, (bf*)awk, bk, nullptr, (bf*)ka, nullptr, KAUG, 1.0f);
    mma_gemm<5><<<gp, 256>>>((bf*)xv, (bf*)awv, bv, nullptr, (bf*)vth, (bf*)vtl, KAUG, 1.0f);

    static bool init = false;
    if (!init) {
        cudaFuncSetAttribute(flash_attn, cudaFuncAttributeMaxDynamicSharedMemorySize,
                             SMEM_TOTAL_FA);
        init = true;
    }
    flash_attn<<<dim3(SEQ / 128, ZH), 256, SMEM_TOTAL_FA>>>(
        (bf*)qa, (bf*)ka, (bf*)vth, (bf*)vtl, mask, (bf*)ca);

    mma_gemm<0><<<gp, 256>>>((bf*)ca, (bf*)awo, bo, (float*)d_out, nullptr, nullptr, KAUG, 1.0f);
}

// round 8
// speedup vs baseline: 2.6588x; 1.3126x over previous
#include <cuda_runtime.h>
#include <cuda_bf16.h>
#include <math.h>
#include <stdint.h>

typedef __nv_bfloat16 bf;

#define SEQ   2048
#define DM    1024
#define NH    16
#define HD    64
#define MROWS 4096
#define ZH    32

// ---------------------------------------------------------------------------
// Scratch (__device__ globals; no allocations allowed) — 64 MB total
// ---------------------------------------------------------------------------
__device__ bf g_qh[MROWS*DM], g_ql[MROWS*DM];     // projected Q hi/lo (pre-scaled)
__device__ bf g_kh[MROWS*DM], g_kl[MROWS*DM];     // projected K hi/lo
__device__ bf g_vth[ZH*HD*SEQ], g_vtl[ZH*HD*SEQ]; // projected V^T per head hi/lo
__device__ bf g_ch[MROWS*DM], g_cl[MROWS*DM];     // context hi/lo

// ---------------------------------------------------------------------------
// PTX helpers (plain sm_103-legal: mma.sync / ldmatrix / cp.async)
// ---------------------------------------------------------------------------
__device__ __forceinline__ uint32_t su32(const void* p) {
    uint32_t a;
    asm("{ .reg .u64 t; cvta.to.shared.u64 t, %1; cvt.u32.u64 %0, t; }" : "=r"(a) : "l"(p));
    return a;
}
#define CPASYNC(d, s) asm volatile("cp.async.cg.shared.global [%0], [%1], 16;" :: "r"(d), "l"(s))
#define CPCOMMIT()    asm volatile("cp.async.commit_group;")
#define CPWAIT0()     asm volatile("cp.async.wait_group 0;")
#define CPWAIT1()     asm volatile("cp.async.wait_group 1;")

__device__ __forceinline__ void ldm4(uint32_t* r, uint32_t addr) {
    asm volatile("ldmatrix.sync.aligned.m8n8.x4.shared.b16 {%0,%1,%2,%3}, [%4];"
                 : "=r"(r[0]), "=r"(r[1]), "=r"(r[2]), "=r"(r[3]) : "r"(addr));
}
__device__ __forceinline__ void mma16816(float* c, const uint32_t* a, uint32_t b0, uint32_t b1) {
    asm volatile("mma.sync.aligned.m16n8k16.row.col.f32.bf16.bf16.f32 "
                 "{%0,%1,%2,%3}, {%4,%5,%6,%7}, {%8,%9}, {%0,%1,%2,%3};"
                 : "+f"(c[0]), "+f"(c[1]), "+f"(c[2]), "+f"(c[3])
                 : "r"(a[0]), "r"(a[1]), "r"(a[2]), "r"(a[3]), "r"(b0), "r"(b1));
}
__device__ __forceinline__ void bsplit(float x, bf& h, bf& l) {
    h = __float2bfloat16(x);
    l = __float2bfloat16(x - __bfloat162float(h));
}
__device__ __forceinline__ float bhi(float x) {
    return __bfloat162float(__float2bfloat16(x));
}
__device__ __forceinline__ uint32_t pk2(float lo, float hi) {   // {lo@0-15, hi@16-31}
    uint32_t r;
    asm("cvt.rn.bf16x2.f32 %0, %1, %2;" : "=r"(r) : "f"(hi), "f"(lo));
    return r;
}

// ---------------------------------------------------------------------------
// Fused Q/K/V projection GEMM with in-kernel fp32 -> bf16 hi/lo conversion.
// C[M=4096, N=1024] = X @ W^T (+bias), 3-term split-bf16 MMA.
// grid (8, 32, 3): z=0 Q (scaled, planar hi/lo), z=1 K (planar), z=2 V (transposed).
// 128x128 tile, BK=32, 256 threads, reg-prefetch + single smem buffer.
// ---------------------------------------------------------------------------
__global__ void __launch_bounds__(256, 1)
qkv_gemm(const float* __restrict__ xq, const float* __restrict__ xk,
         const float* __restrict__ xv,
         const float* __restrict__ wq, const float* __restrict__ wk,
         const float* __restrict__ wv,
         const float* __restrict__ bq, const float* __restrict__ bk,
         const float* __restrict__ bv,
         bf* __restrict__ qh, bf* __restrict__ ql,
         bf* __restrict__ kh, bf* __restrict__ kl,
         bf* __restrict__ vth, bf* __restrict__ vtl)
{
    __shared__ __align__(16) bf Ah[128][40], Al[128][40], Bh[128][40], Bl[128][40];

    const int tid = threadIdx.x, lane = tid & 31, wid = tid >> 5;
    const int m0 = blockIdx.y * 128, n0 = blockIdx.x * 128, z = blockIdx.z;
    const float* X  = (z == 0) ? xq : (z == 1) ? xk : xv;
    const float* W  = (z == 0) ? wq : (z == 1) ? wk : wv;
    const float* Bi = (z == 0) ? bq : (z == 1) ? bk : bv;

    float ar[16], br[16];
    auto ldg = [&](int kb) {
        #pragma unroll
        for (int i = 0; i < 4; i++) {
            int id = tid + 256 * i;
            int r = id >> 3, c = (id & 7) * 4;
            *(float4*)(ar + 4 * i) = *(const float4*)(X + (size_t)(m0 + r) * DM + kb + c);
            *(float4*)(br + 4 * i) = *(const float4*)(W + (size_t)(n0 + r) * DM + kb + c);
        }
    };
    auto sts = [&]() {
        #pragma unroll
        for (int i = 0; i < 4; i++) {
            int id = tid + 256 * i;
            int r = id >> 3, c = (id & 7) * 4;
            #pragma unroll
            for (int u = 0; u < 4; u += 2) {
                bf h0, l0, h1, l1;
                bsplit(ar[4 * i + u], h0, l0); bsplit(ar[4 * i + u + 1], h1, l1);
                *(__nv_bfloat162*)&Ah[r][c + u] = __nv_bfloat162(h0, h1);
                *(__nv_bfloat162*)&Al[r][c + u] = __nv_bfloat162(l0, l1);
                bsplit(br[4 * i + u], h0, l0); bsplit(br[4 * i + u + 1], h1, l1);
                *(__nv_bfloat162*)&Bh[r][c + u] = __nv_bfloat162(h0, h1);
                *(__nv_bfloat162*)&Bl[r][c + u] = __nv_bfloat162(l0, l1);
            }
        }
    };

    const int wm = wid >> 1, wn = wid & 1;
    float acc[2][8][4];
    #pragma unroll
    for (int i = 0; i < 2; i++)
        #pragma unroll
        for (int j = 0; j < 8; j++)
            #pragma unroll
            for (int t = 0; t < 4; t++) acc[i][j][t] = 0.f;

    const int frow = ((lane >> 3) & 1) * 8 + (lane & 7);
    const int fcol = ((lane >> 4) & 1) * 8;

    ldg(0); sts(); __syncthreads();
    for (int kt = 0; kt < 32; kt++) {
        if (kt < 31) ldg((kt + 1) * 32);
        #pragma unroll
        for (int k16 = 0; k16 < 2; k16++) {
            uint32_t ah[2][4], al[2][4];
            #pragma unroll
            for (int i = 0; i < 2; i++) {
                ldm4(ah[i], su32(&Ah[wm * 32 + i * 16 + frow][k16 * 16 + fcol]));
                ldm4(al[i], su32(&Al[wm * 32 + i * 16 + frow][k16 * 16 + fcol]));
            }
            #pragma unroll
            for (int j = 0; j < 4; j++) {
                uint32_t bh4[4], bl4[4];
                ldm4(bh4, su32(&Bh[wn * 64 + j * 16 + frow][k16 * 16 + fcol]));
                ldm4(bl4, su32(&Bl[wn * 64 + j * 16 + frow][k16 * 16 + fcol]));
                #pragma unroll
                for (int i = 0; i < 2; i++) {
                    mma16816(acc[i][2 * j],     ah[i], bh4[0], bh4[2]);
                    mma16816(acc[i][2 * j + 1], ah[i], bh4[1], bh4[3]);
                    mma16816(acc[i][2 * j],     al[i], bh4[0], bh4[2]);
                    mma16816(acc[i][2 * j + 1], al[i], bh4[1], bh4[3]);
                    mma16816(acc[i][2 * j],     ah[i], bl4[0], bl4[2]);
                    mma16816(acc[i][2 * j + 1], ah[i], bl4[1], bl4[3]);
                }
            }
        }
        __syncthreads();
        if (kt < 31) { sts(); __syncthreads(); }
    }

    const int er = lane >> 2, ec = (lane & 3) * 2;
    #pragma unroll
    for (int i = 0; i < 2; i++) {
        #pragma unroll
        for (int j = 0; j < 8; j++) {
            #pragma unroll
            for (int h2 = 0; h2 < 2; h2++) {
                int rr = m0 + wm * 32 + i * 16 + er + h2 * 8;
                int nb = n0 + wn * 64 + j * 8 + ec;
                #pragma unroll
                for (int t = 0; t < 2; t++) {
                    int n = nb + t;
                    float x = acc[i][j][h2 * 2 + t] + Bi[n];
                    bf hi, lo;
                    if (z == 0) {
                        x *= 0.125f;
                        bsplit(x, hi, lo);
                        qh[(size_t)rr * DM + n] = hi; ql[(size_t)rr * DM + n] = lo;
                    } else if (z == 1) {
                        bsplit(x, hi, lo);
                        kh[(size_t)rr * DM + n] = hi; kl[(size_t)rr * DM + n] = lo;
                    } else {
                        int hh = n >> 6, d = n & 63;
                        int zz = (rr >> 11) * NH + hh, s = rr & 2047;
                        size_t base = (size_t)zz * HD * SEQ + (size_t)d * SEQ + s;
                        bsplit(x, hi, lo);
                        vth[base] = hi; vtl[base] = lo;
                    }
                }
            }
        }
    }
}

// ---------------------------------------------------------------------------
// Output projection: d_out = ctx @ wo^T + bo.  ctx comes as bf16 hi/lo planes,
// wo is fp32 converted in-kernel. Same 3-term MMA skeleton.
// ---------------------------------------------------------------------------
__global__ void __launch_bounds__(256, 1)
oproj_gemm(const bf* __restrict__ Ch, const bf* __restrict__ Cl,
           const float* __restrict__ W, const float* __restrict__ Bi,
           float* __restrict__ Out)
{
    __shared__ __align__(16) bf Ah[128][40], Al[128][40], Bh[128][40], Bl[128][40];

    const int tid = threadIdx.x, lane = tid & 31, wid = tid >> 5;
    const int m0 = blockIdx.y * 128, n0 = blockIdx.x * 128;

    uint2 arh[4], arl[4];
    float br[16];
    auto ldg = [&](int kb) {
        #pragma unroll
        for (int i = 0; i < 4; i++) {
            int id = tid + 256 * i;
            int r = id >> 3, c = (id & 7) * 4;
            arh[i] = *(const uint2*)(Ch + (size_t)(m0 + r) * DM + kb + c);
            arl[i] = *(const uint2*)(Cl + (size_t)(m0 + r) * DM + kb + c);
            *(float4*)(br + 4 * i) = *(const float4*)(W + (size_t)(n0 + r) * DM + kb + c);
        }
    };
    auto sts = [&]() {
        #pragma unroll
        for (int i = 0; i < 4; i++) {
            int id = tid + 256 * i;
            int r = id >> 3, c = (id & 7) * 4;
            *(uint2*)&Ah[r][c] = arh[i];
            *(uint2*)&Al[r][c] = arl[i];
            #pragma unroll
            for (int u = 0; u < 4; u += 2) {
                bf h0, l0, h1, l1;
                bsplit(br[4 * i + u], h0, l0); bsplit(br[4 * i + u + 1], h1, l1);
                *(__nv_bfloat162*)&Bh[r][c + u] = __nv_bfloat162(h0, h1);
                *(__nv_bfloat162*)&Bl[r][c + u] = __nv_bfloat162(l0, l1);
            }
        }
    };

    const int wm = wid >> 1, wn = wid & 1;
    float acc[2][8][4];
    #pragma unroll
    for (int i = 0; i < 2; i++)
        #pragma unroll
        for (int j = 0; j < 8; j++)
            #pragma unroll
            for (int t = 0; t < 4; t++) acc[i][j][t] = 0.f;

    const int frow = ((lane >> 3) & 1) * 8 + (lane & 7);
    const int fcol = ((lane >> 4) & 1) * 8;

    ldg(0); sts(); __syncthreads();
    for (int kt = 0; kt < 32; kt++) {
        if (kt < 31) ldg((kt + 1) * 32);
        #pragma unroll
        for (int k16 = 0; k16 < 2; k16++) {
            uint32_t ah[2][4], al[2][4];
            #pragma unroll
            for (int i = 0; i < 2; i++) {
                ldm4(ah[i], su32(&Ah[wm * 32 + i * 16 + frow][k16 * 16 + fcol]));
                ldm4(al[i], su32(&Al[wm * 32 + i * 16 + frow][k16 * 16 + fcol]));
            }
            #pragma unroll
            for (int j = 0; j < 4; j++) {
                uint32_t bh4[4], bl4[4];
                ldm4(bh4, su32(&Bh[wn * 64 + j * 16 + frow][k16 * 16 + fcol]));
                ldm4(bl4, su32(&Bl[wn * 64 + j * 16 + frow][k16 * 16 + fcol]));
                #pragma unroll
                for (int i = 0; i < 2; i++) {
                    mma16816(acc[i][2 * j],     ah[i], bh4[0], bh4[2]);
                    mma16816(acc[i][2 * j + 1], ah[i], bh4[1], bh4[3]);
                    mma16816(acc[i][2 * j],     al[i], bh4[0], bh4[2]);
                    mma16816(acc[i][2 * j + 1], al[i], bh4[1], bh4[3]);
                    mma16816(acc[i][2 * j],     ah[i], bl4[0], bl4[2]);
                    mma16816(acc[i][2 * j + 1], ah[i], bl4[1], bl4[3]);
                }
            }
        }
        __syncthreads();
        if (kt < 31) { sts(); __syncthreads(); }
    }

    const int er = lane >> 2, ec = (lane & 3) * 2;
    #pragma unroll
    for (int i = 0; i < 2; i++) {
        #pragma unroll
        for (int j = 0; j < 8; j++) {
            #pragma unroll
            for (int h2 = 0; h2 < 2; h2++) {
                int rr = m0 + wm * 32 + i * 16 + er + h2 * 8;
                int nb = n0 + wn * 64 + j * 8 + ec;
                Out[(size_t)rr * DM + nb]     = acc[i][j][h2 * 2 + 0] + Bi[nb];
                Out[(size_t)rr * DM + nb + 1] = acc[i][j][h2 * 2 + 1] + Bi[nb + 1];
            }
        }
    }
}

// ---------------------------------------------------------------------------
// Fused flash attention (planar hi/lo). Block = 128 queries x 1 head.
// Q/K smem tiles: cols 0-63 hi, 64-127 lo. S = QhKh + QlKh + QhKl.
// PV = Ph·Vh + Pl·Vh + Ph·Vl. ctx written as hi/lo planes.
// ---------------------------------------------------------------------------
#define FA_QS    0
#define FA_KS    17408                    // Q: 128 x 136
#define FA_VS    34816                    // K: 2 buf x 64 x 136
#define FA_MSK_B 106496                   // after V: 2 buf x 2 planes x 64 x 72
#define FA_FLG_B 114688
#define FA_SMEM  114816

__global__ void __launch_bounds__(256, 1)
flash_attn(const bf* __restrict__ Qh, const bf* __restrict__ Ql,
           const bf* __restrict__ Kh, const bf* __restrict__ Kl,
           const bf* __restrict__ Vh, const bf* __restrict__ Vl,
           const int* __restrict__ mask,
           bf* __restrict__ Ch, bf* __restrict__ Cl)
{
    extern __shared__ __align__(16) bf sm[];
    bf* Qs = sm + FA_QS;
    bf* Ks = sm + FA_KS;
    bf* Vs = sm + FA_VS;
    int* msk = (int*)((char*)sm + FA_MSK_B);
    int* flg = (int*)((char*)sm + FA_FLG_B);

    const int tid = threadIdx.x, lane = tid & 31, w = tid >> 5;
    const int qb = blockIdx.x, z = blockIdx.y;
    const int b = z >> 4, h = z & 15;

    const bf* Qhp = Qh + ((size_t)(b * SEQ + qb * 128)) * DM + h * HD;
    const bf* Qlp = Ql + ((size_t)(b * SEQ + qb * 128)) * DM + h * HD;
    const bf* Khp = Kh + ((size_t)(b * SEQ)) * DM + h * HD;
    const bf* Klp = Kl + ((size_t)(b * SEQ)) * DM + h * HD;
    const bf* Vhp = Vh + (size_t)z * HD * SEQ;
    const bf* Vlp = Vl + (size_t)z * HD * SEQ;

    if (tid < 32) flg[tid] = 0;
    __syncthreads();
    #pragma unroll
    for (int i = 0; i < 8; i++) {
        int k = tid + i * 256;
        int m = mask[b * SEQ + k];
        msk[k] = m;
        if (m == 0) flg[k >> 6] = 1;
    }

    // Q tile: 128 rows x (64 hi | 64 lo)
    {
        int r = tid >> 1, q = tid & 1;      // 2 chunks of 4 per plane per... 8 total
        #pragma unroll
        for (int i = 0; i < 4; i++) {
            int cc = (q + i * 2) * 8;       // 0..56
            CPASYNC(su32(Qs + r * 136 + cc),      Qhp + (size_t)r * DM + cc);
            CPASYNC(su32(Qs + r * 136 + 64 + cc), Qlp + (size_t)r * DM + cc);
        }
    }
    auto loadKV = [&](int kb, int st) {
        int r = tid >> 2, q = tid & 3;      // r 0..63
        #pragma unroll
        for (int i = 0; i < 2; i++) {
            int cc = (q + i * 4) * 8;       // 0..56
            CPASYNC(su32(Ks + st * 8704 + r * 136 + cc),
                    Khp + (size_t)(kb * 64 + r) * DM + cc);
            CPASYNC(su32(Ks + st * 8704 + r * 136 + 64 + cc),
                    Klp + (size_t)(kb * 64 + r) * DM + cc);
            CPASYNC(su32(Vs + st * 9216 + r * 72 + cc),
                    Vhp + (size_t)r * SEQ + kb * 64 + cc);
            CPASYNC(su32(Vs + st * 9216 + 4608 + r * 72 + cc),
                    Vlp + (size_t)r * SEQ + kb * 64 + cc);
        }
    };
    loadKV(0, 0); CPCOMMIT();

    const int frow = ((lane >> 3) & 1) * 8 + (lane & 7);
    const int fcol = ((lane >> 4) & 1) * 8;
    const int er = lane >> 2, ec = (lane & 3) * 2;

    uint32_t qf[8][4];
    float Oa[8][4];
    #pragma unroll
    for (int j = 0; j < 8; j++)
        #pragma unroll
        for (int t = 0; t < 4; t++) Oa[j][t] = 0.f;
    float mrow[2] = { -1e30f, -1e30f }, lrow[2] = { 0.f, 0.f };

    for (int kb = 0; kb < 32; kb++) {
        const int st = kb & 1;
        if (kb + 1 < 32) { loadKV(kb + 1, st ^ 1); CPCOMMIT(); CPWAIT1(); }
        else             { CPWAIT0(); }
        __syncthreads();
        if (kb == 0) {
            #pragma unroll
            for (int k16 = 0; k16 < 8; k16++)
                ldm4(qf[k16], su32(Qs + (w * 16 + frow) * 136 + k16 * 16 + fcol));
        }

        // ---- S = QhKh + QlKh + QhKl (16 x 64 per warp) ----
        float Sa[8][4];
        #pragma unroll
        for (int j = 0; j < 8; j++)
            #pragma unroll
            for (int t = 0; t < 4; t++) Sa[j][t] = 0.f;

        const bf* kbuf = Ks + st * 8704;
        #pragma unroll
        for (int j = 0; j < 4; j++) {
            #pragma unroll
            for (int k = 0; k < 4; k++) {
                uint32_t bh4[4], bl4[4];
                ldm4(bh4, su32(kbuf + (j * 16 + frow) * 136 + k * 16 + fcol));
                ldm4(bl4, su32(kbuf + (j * 16 + frow) * 136 + (k + 4) * 16 + fcol));
                mma16816(Sa[2 * j],     qf[k],     bh4[0], bh4[2]);
                mma16816(Sa[2 * j + 1], qf[k],     bh4[1], bh4[3]);
                mma16816(Sa[2 * j],     qf[k + 4], bh4[0], bh4[2]);
                mma16816(Sa[2 * j + 1], qf[k + 4], bh4[1], bh4[3]);
                mma16816(Sa[2 * j],     qf[k],     bl4[0], bl4[2]);
                mma16816(Sa[2 * j + 1], qf[k],     bl4[1], bl4[3]);
            }
        }

        // ---- mask ----
        if (flg[kb]) {
            #pragma unroll
            for (int j = 0; j < 8; j++) {
                int c0 = kb * 64 + j * 8 + ec;
                if (!msk[c0])     { Sa[j][0] = -1e9f; Sa[j][2] = -1e9f; }
                if (!msk[c0 + 1]) { Sa[j][1] = -1e9f; Sa[j][3] = -1e9f; }
            }
        }

        // ---- online softmax (rows er, er+8) ----
        float mx0 = -1e30f, mx1 = -1e30f;
        #pragma unroll
        for (int j = 0; j < 8; j++) {
            mx0 = fmaxf(mx0, fmaxf(Sa[j][0], Sa[j][1]));
            mx1 = fmaxf(mx1, fmaxf(Sa[j][2], Sa[j][3]));
        }
        #pragma unroll
        for (int o = 1; o <= 2; o <<= 1) {
            mx0 = fmaxf(mx0, __shfl_xor_sync(0xffffffffu, mx0, o));
            mx1 = fmaxf(mx1, __shfl_xor_sync(0xffffffffu, mx1, o));
        }
        float nm0 = fmaxf(mrow[0], mx0), nm1 = fmaxf(mrow[1], mx1);
        float cor0 = __expf(mrow[0] - nm0), cor1 = __expf(mrow[1] - nm1);
        mrow[0] = nm0; mrow[1] = nm1;

        float rs0 = 0.f, rs1 = 0.f;
        #pragma unroll
        for (int j = 0; j < 8; j++) {
            Sa[j][0] = __expf(Sa[j][0] - nm0); rs0 += Sa[j][0];
            Sa[j][1] = __expf(Sa[j][1] - nm0); rs0 += Sa[j][1];
            Sa[j][2] = __expf(Sa[j][2] - nm1); rs1 += Sa[j][2];
            Sa[j][3] = __expf(Sa[j][3] - nm1); rs1 += Sa[j][3];
        }
        #pragma unroll
        for (int o = 1; o <= 2; o <<= 1) {
            rs0 += __shfl_xor_sync(0xffffffffu, rs0, o);
            rs1 += __shfl_xor_sync(0xffffffffu, rs1, o);
        }
        lrow[0] = lrow[0] * cor0 + rs0;
        lrow[1] = lrow[1] * cor1 + rs1;
        #pragma unroll
        for (int j = 0; j < 8; j++) {
            Oa[j][0] *= cor0; Oa[j][1] *= cor0;
            Oa[j][2] *= cor1; Oa[j][3] *= cor1;
        }

        // ---- PV: O += Ph·Vh + Pl·Vh + Ph·Vl ----
        const bf* vh = Vs + st * 9216;
        const bf* vl = vh + 4608;
        #pragma unroll
        for (int c = 0; c < 4; c++) {
            float a0 = Sa[2*c][0], a1 = Sa[2*c][1], a2 = Sa[2*c][2], a3 = Sa[2*c][3];
            float b0 = Sa[2*c+1][0], b1 = Sa[2*c+1][1], b2 = Sa[2*c+1][2], b3 = Sa[2*c+1][3];
            uint32_t ph[4], pl[4];
            ph[0] = pk2(a0, a1); ph[1] = pk2(a2, a3);
            ph[2] = pk2(b0, b1); ph[3] = pk2(b2, b3);
            pl[0] = pk2(a0 - bhi(a0), a1 - bhi(a1));
            pl[1] = pk2(a2 - bhi(a2), a3 - bhi(a3));
            pl[2] = pk2(b0 - bhi(b0), b1 - bhi(b1));
            pl[3] = pk2(b2 - bhi(b2), b3 - bhi(b3));
            #pragma unroll
            for (int t = 0; t < 4; t++) {
                uint32_t bh4[4], bl4[4];
                ldm4(bh4, su32(vh + (t * 16 + frow) * 72 + c * 16 + fcol));
                ldm4(bl4, su32(vl + (t * 16 + frow) * 72 + c * 16 + fcol));
                mma16816(Oa[2 * t],     ph, bh4[0], bh4[2]);
                mma16816(Oa[2 * t + 1], ph, bh4[1], bh4[3]);
                mma16816(Oa[2 * t],     pl, bh4[0], bh4[2]);
                mma16816(Oa[2 * t + 1], pl, bh4[1], bh4[3]);
                mma16816(Oa[2 * t],     ph, bl4[0], bl4[2]);
                mma16816(Oa[2 * t + 1], ph, bl4[1], bl4[3]);
            }
        }
        __syncthreads();
    }

    // ---- epilogue: normalize, write ctx hi/lo planes ----
    float i0 = 1.f / lrow[0], i1 = 1.f / lrow[1];
    int r0g = b * SEQ + qb * 128 + w * 16 + er;
    size_t base0 = (size_t)r0g * DM + h * HD;
    size_t base1 = base0 + (size_t)8 * DM;
    #pragma unroll
    for (int j = 0; j < 8; j++) {
        int d0 = j * 8 + ec;
        float v00 = Oa[j][0] * i0, v01 = Oa[j][1] * i0;
        float v10 = Oa[j][2] * i1, v11 = Oa[j][3] * i1;
        bf h00, l00, h01, l01, h10, l10, h11, l11;
        bsplit(v00, h00, l00); bsplit(v01, h01, l01);
        bsplit(v10, h10, l10); bsplit(v11, h11, l11);
        *(__nv_bfloat162*)(Ch + base0 + d0) = __nv_bfloat162(h00, h01);
        *(__nv_bfloat162*)(Cl + base0 + d0) = __nv_bfloat162(l00, l01);
        *(__nv_bfloat162*)(Ch + base1 + d0) = __nv_bfloat162(h10, h11);
        *(__nv_bfloat162*)(Cl + base1 + d0) = __nv_bfloat162(l10, l11);
    }
}

// ---------------------------------------------------------------------------
extern "C" void kernel_launch(void* const* d_in, const int* in_sizes, int n_in,
                              void* d_out, int out_size)
{
    const float* query = (const float*)d_in[0];
    const float* key   = (const float*)d_in[1];
    const float* value = (const float*)d_in[2];
    const int*   mask  = (const int*)d_in[3];
    const float* wq = (const float*)d_in[4];  const float* bq = (const float*)d_in[5];
    const float* wk = (const float*)d_in[6];  const float* bk = (const float*)d_in[7];
    const float* wv = (const float*)d_in[8];  const float* bv = (const float*)d_in[9];
    const float* wo = (const float*)d_in[10]; const float* bo = (const float*)d_in[11];

    #define SYM(p, sname) void* p; cudaGetSymbolAddress(&p, sname)
    SYM(qh, g_qh); SYM(ql, g_ql); SYM(kh, g_kh); SYM(kl, g_kl);
    SYM(vth, g_vth); SYM(vtl, g_vtl); SYM(ch, g_ch); SYM(cl, g_cl);
    #undef SYM

    static bool init = false;
    if (!init) {
        cudaFuncSetAttribute(flash_attn, cudaFuncAttributeMaxDynamicSharedMemorySize,
                             FA_SMEM);
        init = true;
    }

    qkv_gemm<<<dim3(8, 32, 3), 256>>>(query, key, value, wq, wk, wv, bq, bk, bv,
                                      (bf*)qh, (bf*)ql, (bf*)kh, (bf*)kl,
                                      (bf*)vth, (bf*)vtl);

    flash_attn<<<dim3(SEQ / 128, ZH), 256, FA_SMEM>>>(
        (bf*)qh, (bf*)ql, (bf*)kh, (bf*)kl, (bf*)vth, (bf*)vtl, mask,
        (bf*)ch, (bf*)cl);

    oproj_gemm<<<dim3(8, 32), 256>>>((bf*)ch, (bf*)cl, wo, bo, (float*)d_out);
}